// round 5
// baseline (speedup 1.0000x reference)
#include <cuda_runtime.h>
#include <stdint.h>

#define HH 512
#define WW 512
#define NB 2
#define NC 4
#define NMASK (NB*NC)
#define NPIX (NB*HH*WW)

// Scratch: 1D row distances (clamped) for each (n,c) mask (pos) and complement (neg)
__device__ unsigned short gp_buf[(size_t)NMASK*HH*WW];
__device__ unsigned short gn_buf[(size_t)NMASK*HH*WW];
__device__ double g_acc;            // static-init 0; reset by last loss block
__device__ unsigned int g_count;    // static-init 0; reset by last loss block
__device__ int g_present[NMASK];    // static-init 0; reset by last loss block

// ---------------------------------------------------------------------------
// Kernel 1: row pass. One block per (n, r). 4 warps, one per class.
// Inline dtype probe: for little-endian int64 labels (0..3) all odd 32-bit
// words are zero; if any odd word in this row's chunk is nonzero -> int32.
// Computes g = min(dist_to_False_left, dist_to_False_right) for mask (t==c)
// and complement (t!=c), matching reference scan semantics (carry init 1e6).
// ---------------------------------------------------------------------------
__global__ void __launch_bounds__(128) row_pass(const int* __restrict__ tgt_words) {
    __shared__ unsigned char cls[WW];
    __shared__ int dfp[NC][WW];   // forward (left) distance, pos mask
    __shared__ int dfn[NC][WW];   // forward (left) distance, neg mask

    const int blk = blockIdx.x;          // n*H + r
    const int n = blk >> 9;
    const int r = blk & (HH - 1);
    const int tid = threadIdx.x;

    const size_t elem_base = ((size_t)n * HH + r) * WW;

    // Probe + load: read this row as int32 view (always in-bounds for both dtypes)
    const int4 v = reinterpret_cast<const int4*>(tgt_words + elem_base)[tid];
    const int myodd = v.y | v.w;
    if (__syncthreads_or(myodd)) {
        // int32 labels: v holds labels x = 4*tid .. 4*tid+3
        cls[4 * tid + 0] = (unsigned char)v.x;
        cls[4 * tid + 1] = (unsigned char)v.y;
        cls[4 * tid + 2] = (unsigned char)v.z;
        cls[4 * tid + 3] = (unsigned char)v.w;
    } else {
        // int64 labels: reload as longlong4 (4 labels per thread)
        const longlong4 q = reinterpret_cast<const longlong4*>(
            tgt_words + 2 * elem_base)[tid];
        cls[4 * tid + 0] = (unsigned char)q.x;
        cls[4 * tid + 1] = (unsigned char)q.y;
        cls[4 * tid + 2] = (unsigned char)q.z;
        cls[4 * tid + 3] = (unsigned char)q.w;
    }
    __syncthreads();

    const int lane = tid & 31;
    const int c = tid >> 5;              // class handled by this warp

    const int KBIG = 1 << 20;
    const int SINF = 1 << 26;
    const unsigned FULL = 0xffffffffu;

    // ---------------- forward (left-to-right) ----------------
    {
        unsigned char cl[16];
        int dp = KBIG, dn = KBIG;
        bool found = false;
        #pragma unroll
        for (int i = 0; i < 16; i++) {
            cl[i] = cls[lane * 16 + i];
            bool m = (cl[i] == (unsigned char)c);
            found |= m;
            dp = m ? dp + 1 : 0;
            dn = m ? 0 : dn + 1;
        }
        int sp = (dp >= KBIG) ? SINF : dp;
        int sn = (dn >= KBIG) ? SINF : dn;
        #pragma unroll
        for (int off = 1; off < 32; off <<= 1) {
            int up_p = __shfl_up_sync(FULL, sp, off);
            int up_n = __shfl_up_sync(FULL, sn, off);
            if (lane >= off) {
                sp = min(up_p + 16 * off, sp);
                sn = min(up_n + 16 * off, sn);
            }
        }
        int ep = __shfl_up_sync(FULL, sp, 1);
        int en = __shfl_up_sync(FULL, sn, 1);
        int carp = (lane == 0) ? 1000000 : min(1000000 + 16 * lane, ep);
        int carn = (lane == 0) ? 1000000 : min(1000000 + 16 * lane, en);
        #pragma unroll
        for (int i = 0; i < 16; i++) {
            bool m = (cl[i] == (unsigned char)c);
            carp = m ? carp + 1 : 0;
            carn = m ? 0 : carn + 1;
            dfp[c][lane * 16 + i] = carp;
            dfn[c][lane * 16 + i] = carn;
        }
        if (__any_sync(FULL, found) && lane == 0)
            atomicOr(&g_present[n * NC + c], 1);
    }
    __syncwarp();

    // ---------------- backward (right-to-left), combine, write g ----------------
    {
        unsigned char cl[16];
        int dp = KBIG, dn = KBIG;
        #pragma unroll
        for (int i = 0; i < 16; i++) {
            cl[i] = cls[WW - 1 - lane * 16 - i];
            bool m = (cl[i] == (unsigned char)c);
            dp = m ? dp + 1 : 0;
            dn = m ? 0 : dn + 1;
        }
        int sp = (dp >= KBIG) ? SINF : dp;
        int sn = (dn >= KBIG) ? SINF : dn;
        #pragma unroll
        for (int off = 1; off < 32; off <<= 1) {
            int up_p = __shfl_up_sync(FULL, sp, off);
            int up_n = __shfl_up_sync(FULL, sn, off);
            if (lane >= off) {
                sp = min(up_p + 16 * off, sp);
                sn = min(up_n + 16 * off, sn);
            }
        }
        int ep = __shfl_up_sync(FULL, sp, 1);
        int en = __shfl_up_sync(FULL, sn, 1);
        int carp = (lane == 0) ? 1000000 : min(1000000 + 16 * lane, ep);
        int carn = (lane == 0) ? 1000000 : min(1000000 + 16 * lane, en);

        unsigned short* gp = gp_buf + ((size_t)(n * NC + c) * HH + r) * WW;
        unsigned short* gn = gn_buf + ((size_t)(n * NC + c) * HH + r) * WW;
        #pragma unroll
        for (int i = 0; i < 16; i++) {
            int x = WW - 1 - lane * 16 - i;
            bool m = (cl[i] == (unsigned char)c);
            carp = m ? carp + 1 : 0;
            carn = m ? 0 : carn + 1;
            int gpv = min(min(carp, dfp[c][x]), 60000);
            int gnv = min(min(carn, dfn[c][x]), 60000);
            gp[x] = (unsigned short)gpv;
            gn[x] = (unsigned short)gnv;
        }
    }
}

// ---------------------------------------------------------------------------
// Column min-plus with batched window + early exit:
//   exact min_{r'} (r-r')^2 + g[r',x]^2
// Window d=1..3 loaded unconditionally (MLP), serial tail from d=4 (rare).
// Extra candidates never lower the true min incorrectly (monotone dd).
// ---------------------------------------------------------------------------
__device__ __forceinline__ float edt2(const unsigned short* __restrict__ col, int r) {
    float v0 = (float)col[r * WW];
    float best = v0 * v0;
    if (best > 1.0f) {
        float u1 = (r >= 1)      ? (float)col[(r - 1) * WW] : 1.0e9f;
        float d1 = (r + 1 < HH)  ? (float)col[(r + 1) * WW] : 1.0e9f;
        float u2 = (r >= 2)      ? (float)col[(r - 2) * WW] : 1.0e9f;
        float d2 = (r + 2 < HH)  ? (float)col[(r + 2) * WW] : 1.0e9f;
        float u3 = (r >= 3)      ? (float)col[(r - 3) * WW] : 1.0e9f;
        float d3 = (r + 3 < HH)  ? (float)col[(r + 3) * WW] : 1.0e9f;
        best = fminf(best, fminf(u1 * u1 + 1.0f, d1 * d1 + 1.0f));
        best = fminf(best, fminf(u2 * u2 + 4.0f, d2 * d2 + 4.0f));
        best = fminf(best, fminf(u3 * u3 + 9.0f, d3 * d3 + 9.0f));
        #pragma unroll 1
        for (int d = 4; (float)(d * d) < best; ++d) {
            float dd = (float)(d * d);
            int a = r - d, b = r + d;
            bool any = false;
            if (a >= 0)  { float t = (float)col[a * WW]; best = fminf(best, t * t + dd); any = true; }
            if (b < HH)  { float t = (float)col[b * WW]; best = fminf(best, t * t + dd); any = true; }
            if (!any) break;
        }
    }
    return best;
}

// ---------------------------------------------------------------------------
// Kernel 2: fused softmax + signed EDT + reduction + tail finalize.
// ---------------------------------------------------------------------------
__global__ void __launch_bounds__(256) loss_pass(const float* __restrict__ logits,
                                                 float* __restrict__ out) {
    const int idx = blockIdx.x * blockDim.x + threadIdx.x;
    const int x = idx & (WW - 1);
    const int r = (idx >> 9) & (HH - 1);
    const int n = idx >> 18;
    const int pix = r * WW + x;

    float l[NC];
    #pragma unroll
    for (int c = 0; c < NC; c++)
        l[c] = logits[(n * NC + c) * (HH * WW) + pix];
    float mx = fmaxf(fmaxf(l[0], l[1]), fmaxf(l[2], l[3]));
    float e[NC], s = 0.0f;
    #pragma unroll
    for (int c = 0; c < NC; c++) { e[c] = __expf(l[c] - mx); s += e[c]; }
    float inv_s = 1.0f / s;

    float acc = 0.0f;
    #pragma unroll 1
    for (int c = 1; c < NC; c++) {           // class 0 masked out by reference
        if (!g_present[n * NC + c]) continue;
        const int base = (n * NC + c) * (HH * WW) + x;
        float d2p = edt2(gp_buf + base, r);
        float d2n = edt2(gn_buf + base, r);
        acc += (e[c] * inv_s) * (sqrtf(d2n) - sqrtf(d2p));
    }
    double local = (double)acc;

    // block reduction (double)
    __shared__ double warp_sums[8];
    __shared__ bool is_last;
    const unsigned FULL = 0xffffffffu;
    #pragma unroll
    for (int off = 16; off > 0; off >>= 1)
        local += __shfl_down_sync(FULL, local, off);
    const int lane = threadIdx.x & 31;
    const int wid = threadIdx.x >> 5;
    if (lane == 0) warp_sums[wid] = local;
    __syncthreads();
    if (wid == 0) {
        double v = (lane < 8) ? warp_sums[lane] : 0.0;
        #pragma unroll
        for (int off = 4; off > 0; off >>= 1)
            v += __shfl_down_sync(FULL, v, off);
        if (lane == 0) {
            atomicAdd(&g_acc, v);
            __threadfence();
            unsigned int t = atomicAdd(&g_count, 1u);
            is_last = (t == gridDim.x - 1);
        }
    }
    __syncthreads();
    // Last block finalizes and restores all device state (deterministic replay)
    if (is_last) {
        if (threadIdx.x == 0) {
            __threadfence();
            double total = g_acc;
            // mean over N*C*H*W = 2*4*512*512 = 2^21 elements
            out[0] = (float)(total * (1.0 / 2097152.0));
            g_acc = 0.0;
            g_count = 0u;
        }
        if (threadIdx.x < NMASK) g_present[threadIdx.x] = 0;
    }
}

extern "C" void kernel_launch(void* const* d_in, const int* in_sizes, int n_in,
                              void* d_out, int out_size) {
    const float* logits = (const float*)d_in[0];     // [2,4,512,512] fp32
    const int* tgt_words = (const int*)d_in[1];      // [2,512,512] int32 or int64
    float* out = (float*)d_out;

    row_pass<<<NB * HH, 128>>>(tgt_words);
    loss_pass<<<NPIX / 256, 256>>>(logits, out);
}

// round 6
// speedup vs baseline: 1.3912x; 1.3912x over previous
#include <cuda_runtime.h>
#include <stdint.h>

#define HH 512
#define WW 512
#define NB 2
#define NC 4
#define NMASK (NB*NC)
#define NPIX (NB*HH*WW)

// Scratch: 1D row distances (clamped) per (n,c): pos mask and complement.
__device__ __align__(16) unsigned short gp_buf[(size_t)NMASK*HH*WW];
__device__ __align__(16) unsigned short gn_buf[(size_t)NMASK*HH*WW];
__device__ double g_acc;            // static-init 0; reset by last loss block
__device__ unsigned int g_count;    // static-init 0; reset by last loss block
__device__ int g_present[NMASK];    // static-init 0; reset by last loss block

// ---------------------------------------------------------------------------
// Kernel 1: row pass. One block per (n, r). 4 warps, one per class.
// Inline dtype probe: for little-endian int64 labels (0..3) all odd 32-bit
// words are zero; any nonzero odd word in this row -> int32 layout.
// g = min(dist_to_False_left, dist_to_False_right), reference carry init 1e6.
// Output staged in shared, then written as coalesced uint4 (8 shorts).
// ---------------------------------------------------------------------------
__global__ void __launch_bounds__(128) row_pass(const int* __restrict__ tgt_words) {
    __shared__ unsigned char cls[WW];
    __shared__ unsigned short dfp[NC][WW];   // forward (left) distance, pos mask
    __shared__ unsigned short dfn[NC][WW];   // forward (left) distance, neg mask
    __shared__ __align__(16) unsigned short gps[NC][WW];  // final g, pos
    __shared__ __align__(16) unsigned short gns[NC][WW];  // final g, neg

    const int blk = blockIdx.x;          // n*H + r
    const int n = blk >> 9;
    const int r = blk & (HH - 1);
    const int tid = threadIdx.x;

    const size_t elem_base = ((size_t)n * HH + r) * WW;

    // Probe + load: read row as int32 view (in-bounds for both dtypes)
    const int4 v = reinterpret_cast<const int4*>(tgt_words + elem_base)[tid];
    const int myodd = v.y | v.w;
    if (__syncthreads_or(myodd)) {
        cls[4 * tid + 0] = (unsigned char)v.x;
        cls[4 * tid + 1] = (unsigned char)v.y;
        cls[4 * tid + 2] = (unsigned char)v.z;
        cls[4 * tid + 3] = (unsigned char)v.w;
    } else {
        const longlong4 q = reinterpret_cast<const longlong4*>(
            tgt_words + 2 * elem_base)[tid];
        cls[4 * tid + 0] = (unsigned char)q.x;
        cls[4 * tid + 1] = (unsigned char)q.y;
        cls[4 * tid + 2] = (unsigned char)q.z;
        cls[4 * tid + 3] = (unsigned char)q.w;
    }
    __syncthreads();

    const int lane = tid & 31;
    const int c = tid >> 5;              // class handled by this warp

    const int KBIG = 1 << 20;
    const int SINF = 1 << 26;
    const unsigned FULL = 0xffffffffu;

    // ---------------- forward (left-to-right) ----------------
    {
        unsigned char cl[16];
        int dp = KBIG, dn = KBIG;
        bool found = false;
        #pragma unroll
        for (int i = 0; i < 16; i++) {
            cl[i] = cls[lane * 16 + i];
            bool m = (cl[i] == (unsigned char)c);
            found |= m;
            dp = m ? dp + 1 : 0;
            dn = m ? 0 : dn + 1;
        }
        int sp = (dp >= KBIG) ? SINF : dp;
        int sn = (dn >= KBIG) ? SINF : dn;
        #pragma unroll
        for (int off = 1; off < 32; off <<= 1) {
            int up_p = __shfl_up_sync(FULL, sp, off);
            int up_n = __shfl_up_sync(FULL, sn, off);
            if (lane >= off) {
                sp = min(up_p + 16 * off, sp);
                sn = min(up_n + 16 * off, sn);
            }
        }
        int ep = __shfl_up_sync(FULL, sp, 1);
        int en = __shfl_up_sync(FULL, sn, 1);
        int carp = (lane == 0) ? 1000000 : min(1000000 + 16 * lane, ep);
        int carn = (lane == 0) ? 1000000 : min(1000000 + 16 * lane, en);
        #pragma unroll
        for (int i = 0; i < 16; i++) {
            bool m = (cl[i] == (unsigned char)c);
            carp = m ? carp + 1 : 0;
            carn = m ? 0 : carn + 1;
            dfp[c][lane * 16 + i] = (unsigned short)min(carp, 60000);
            dfn[c][lane * 16 + i] = (unsigned short)min(carn, 60000);
        }
        if (__any_sync(FULL, found) && lane == 0)
            atomicOr(&g_present[n * NC + c], 1);
    }
    __syncwarp();

    // ---------------- backward (right-to-left), combine into shared ----------------
    {
        unsigned char cl[16];
        int dp = KBIG, dn = KBIG;
        #pragma unroll
        for (int i = 0; i < 16; i++) {
            cl[i] = cls[WW - 1 - lane * 16 - i];
            bool m = (cl[i] == (unsigned char)c);
            dp = m ? dp + 1 : 0;
            dn = m ? 0 : dn + 1;
        }
        int sp = (dp >= KBIG) ? SINF : dp;
        int sn = (dn >= KBIG) ? SINF : dn;
        #pragma unroll
        for (int off = 1; off < 32; off <<= 1) {
            int up_p = __shfl_up_sync(FULL, sp, off);
            int up_n = __shfl_up_sync(FULL, sn, off);
            if (lane >= off) {
                sp = min(up_p + 16 * off, sp);
                sn = min(up_n + 16 * off, sn);
            }
        }
        int ep = __shfl_up_sync(FULL, sp, 1);
        int en = __shfl_up_sync(FULL, sn, 1);
        int carp = (lane == 0) ? 1000000 : min(1000000 + 16 * lane, ep);
        int carn = (lane == 0) ? 1000000 : min(1000000 + 16 * lane, en);

        #pragma unroll
        for (int i = 0; i < 16; i++) {
            int x = WW - 1 - lane * 16 - i;
            bool m = (cl[i] == (unsigned char)c);
            carp = m ? carp + 1 : 0;
            carn = m ? 0 : carn + 1;
            int gpv = min(min(carp, (int)dfp[c][x]), 60000);
            int gnv = min(min(carn, (int)dfn[c][x]), 60000);
            gps[c][x] = (unsigned short)gpv;
            gns[c][x] = (unsigned short)gnv;
        }
    }
    __syncthreads();

    // ---------------- coalesced uint4 write-out ----------------
    // Per buffer: NC*WW shorts = 256 uint4; 128 threads -> 2 each.
    const uint4* sgp = reinterpret_cast<const uint4*>(&gps[0][0]);
    const uint4* sgn = reinterpret_cast<const uint4*>(&gns[0][0]);
    uint4* dgp = reinterpret_cast<uint4*>(gp_buf);
    uint4* dgn = reinterpret_cast<uint4*>(gn_buf);
    #pragma unroll
    for (int k = 0; k < 2; k++) {
        int i2 = k * 128 + tid;              // 0..255
        int c2 = i2 >> 6;                    // class
        int j  = i2 & 63;                    // uint4 index within row
        size_t off = ((size_t)(n * NC + c2) * HH + r) * (WW / 8) + j;
        dgp[off] = sgp[i2];
        dgn[off] = sgn[i2];
    }
}

// ---------------------------------------------------------------------------
// Column min-plus for a PAIR of adjacent columns (x even):
//   exact min_{r'} (r-r')^2 + g[r',x]^2  for x and x+1
// Window d=1..3 unconditional (MLP), branchless clamped indices (clamped
// candidates are dominated by earlier-visited true offsets), rare serial tail.
// ---------------------------------------------------------------------------
__device__ __forceinline__ void edt2_pair(const unsigned short* __restrict__ col,
                                          int r, float& b0, float& b1) {
    unsigned int w0 = *reinterpret_cast<const unsigned int*>(col + r * WW);
    float v0a = (float)(w0 & 0xffffu), v0b = (float)(w0 >> 16);
    b0 = v0a * v0a;
    b1 = v0b * v0b;
    if (fmaxf(b0, b1) > 1.0f) {
        #pragma unroll
        for (int d = 1; d <= 3; d++) {
            unsigned int wu = *reinterpret_cast<const unsigned int*>(col + max(r - d, 0) * WW);
            unsigned int wd = *reinterpret_cast<const unsigned int*>(col + min(r + d, HH - 1) * WW);
            float dd = (float)(d * d);
            float ua = (float)(wu & 0xffffu), ub = (float)(wu >> 16);
            float da = (float)(wd & 0xffffu), db = (float)(wd >> 16);
            b0 = fminf(b0, fminf(ua * ua + dd, da * da + dd));
            b1 = fminf(b1, fminf(ub * ub + dd, db * db + dd));
        }
        #pragma unroll 1
        for (int d = 4; (float)(d * d) < fmaxf(b0, b1); ++d) {
            unsigned int wu = *reinterpret_cast<const unsigned int*>(col + max(r - d, 0) * WW);
            unsigned int wd = *reinterpret_cast<const unsigned int*>(col + min(r + d, HH - 1) * WW);
            float dd = (float)(d * d);
            float ua = (float)(wu & 0xffffu), ub = (float)(wu >> 16);
            float da = (float)(wd & 0xffffu), db = (float)(wd >> 16);
            b0 = fminf(b0, fminf(ua * ua + dd, da * da + dd));
            b1 = fminf(b1, fminf(ub * ub + dd, db * db + dd));
        }
    }
}

// ---------------------------------------------------------------------------
// Kernel 2: fused softmax + signed EDT + reduction + tail finalize.
// 2 pixels per thread (adjacent columns), 256 threads/block.
// ---------------------------------------------------------------------------
__global__ void __launch_bounds__(256) loss_pass(const float* __restrict__ logits,
                                                 float* __restrict__ out) {
    const int idx = blockIdx.x * 256 + threadIdx.x;   // pair index
    const int x = (idx & 255) * 2;
    const int r = (idx >> 8) & (HH - 1);
    const int n = idx >> 17;
    const int pix = r * WW + x;

    float l0[NC], l1[NC];
    #pragma unroll
    for (int c = 0; c < NC; c++) {
        float2 v = *reinterpret_cast<const float2*>(
            logits + (size_t)(n * NC + c) * (HH * WW) + pix);
        l0[c] = v.x; l1[c] = v.y;
    }
    float mx0 = fmaxf(fmaxf(l0[0], l0[1]), fmaxf(l0[2], l0[3]));
    float mx1 = fmaxf(fmaxf(l1[0], l1[1]), fmaxf(l1[2], l1[3]));
    float e0[NC], e1[NC], s0 = 0.0f, s1 = 0.0f;
    #pragma unroll
    for (int c = 0; c < NC; c++) {
        e0[c] = __expf(l0[c] - mx0); s0 += e0[c];
        e1[c] = __expf(l1[c] - mx1); s1 += e1[c];
    }
    float inv0 = 1.0f / s0, inv1 = 1.0f / s1;

    float acc0 = 0.0f, acc1 = 0.0f;
    #pragma unroll 1
    for (int c = 1; c < NC; c++) {           // class 0 masked out by reference
        if (!g_present[n * NC + c]) continue;
        const size_t base = (size_t)(n * NC + c) * (HH * WW) + x;
        float d2p0, d2p1, d2n0, d2n1;
        edt2_pair(gp_buf + base, r, d2p0, d2p1);
        edt2_pair(gn_buf + base, r, d2n0, d2n1);
        acc0 += (e0[c] * inv0) * (sqrtf(d2n0) - sqrtf(d2p0));
        acc1 += (e1[c] * inv1) * (sqrtf(d2n1) - sqrtf(d2p1));
    }
    double local = (double)acc0 + (double)acc1;

    // block reduction (double)
    __shared__ double warp_sums[8];
    __shared__ bool is_last;
    const unsigned FULL = 0xffffffffu;
    #pragma unroll
    for (int off = 16; off > 0; off >>= 1)
        local += __shfl_down_sync(FULL, local, off);
    const int lane = threadIdx.x & 31;
    const int wid = threadIdx.x >> 5;
    if (lane == 0) warp_sums[wid] = local;
    __syncthreads();
    if (wid == 0) {
        double v = (lane < 8) ? warp_sums[lane] : 0.0;
        #pragma unroll
        for (int off = 4; off > 0; off >>= 1)
            v += __shfl_down_sync(FULL, v, off);
        if (lane == 0) {
            atomicAdd(&g_acc, v);
            __threadfence();
            unsigned int t = atomicAdd(&g_count, 1u);
            is_last = (t == gridDim.x - 1);
        }
    }
    __syncthreads();
    // Last block finalizes and restores all device state (deterministic replay)
    if (is_last) {
        if (threadIdx.x == 0) {
            __threadfence();
            double total = g_acc;
            // mean over N*C*H*W = 2*4*512*512 = 2^21 elements
            out[0] = (float)(total * (1.0 / 2097152.0));
            g_acc = 0.0;
            g_count = 0u;
        }
        if (threadIdx.x < NMASK) g_present[threadIdx.x] = 0;
    }
}

extern "C" void kernel_launch(void* const* d_in, const int* in_sizes, int n_in,
                              void* d_out, int out_size) {
    const float* logits = (const float*)d_in[0];     // [2,4,512,512] fp32
    const int* tgt_words = (const int*)d_in[1];      // [2,512,512] int32 or int64
    float* out = (float*)d_out;

    row_pass<<<NB * HH, 128>>>(tgt_words);
    loss_pass<<<NPIX / 512, 256>>>(logits, out);
}

// round 8
// speedup vs baseline: 2.3637x; 1.6991x over previous
#include <cuda_runtime.h>
#include <stdint.h>

#define HH 512
#define WW 512
#define NB 2
#define NC 4
#define NCL 3                 // classes 1..3 only (class 0 masked by reference)
#define NPRES (NB*NCL)
#define NPIX (NB*HH*WW)

// Interleaved scratch: per pixel one uint = gp (low 16) | gn (high 16),
// for classes 1..3 only. 2*3*512*512*4 B = 6.3 MB (L2-resident).
__device__ __align__(16) unsigned int gpn_buf[(size_t)NB*NCL*HH*WW];
__device__ double g_acc;            // static-init 0; reset by last loss block
__device__ unsigned int g_count;    // static-init 0; reset by last loss block
__device__ int g_present[NPRES];    // static-init 0; reset by last loss block

// ---------------------------------------------------------------------------
// Kernel 1: row pass. One block per (n, r). 192 threads:
//   warps 0-2: forward scan for classes 1-3; warps 3-5: backward scan.
// Inline dtype probe: int64 labels (0..3) have all odd 32-bit words zero.
// g = min(fwd, bwd) distance-to-False, reference carry init 1e6 (clamped 60000).
// ---------------------------------------------------------------------------
__global__ void __launch_bounds__(192) row_pass(const int* __restrict__ tgt_words) {
    __shared__ unsigned char cls[WW];
    __shared__ unsigned short dfp[NCL][WW], dfn[NCL][WW];   // forward
    __shared__ unsigned short dbp[NCL][WW], dbn[NCL][WW];   // backward
    __shared__ __align__(16) ushort2 gstage[NCL][WW];       // combined (gp,gn)

    const int blk = blockIdx.x;          // n*H + r
    const int n = blk >> 9;
    const int r = blk & (HH - 1);
    const int tid = threadIdx.x;

    const size_t elem_base = ((size_t)n * HH + r) * WW;

    // Probe + load (threads 0..127 cover the row; int32 view always in-bounds)
    int4 v; int myodd = 0;
    if (tid < 128) {
        v = reinterpret_cast<const int4*>(tgt_words + elem_base)[tid];
        myodd = v.y | v.w;
    }
    if (__syncthreads_or(myodd)) {
        if (tid < 128) {
            cls[4 * tid + 0] = (unsigned char)v.x;
            cls[4 * tid + 1] = (unsigned char)v.y;
            cls[4 * tid + 2] = (unsigned char)v.z;
            cls[4 * tid + 3] = (unsigned char)v.w;
        }
    } else {
        if (tid < 128) {
            const longlong4 q = reinterpret_cast<const longlong4*>(
                tgt_words + 2 * elem_base)[tid];
            cls[4 * tid + 0] = (unsigned char)q.x;
            cls[4 * tid + 1] = (unsigned char)q.y;
            cls[4 * tid + 2] = (unsigned char)q.z;
            cls[4 * tid + 3] = (unsigned char)q.w;
        }
    }
    __syncthreads();

    const int warp = tid >> 5;
    const int lane = tid & 31;
    const int KBIG = 1 << 20;
    const int SINF = 1 << 26;
    const unsigned FULL = 0xffffffffu;

    if (warp < NCL) {
        // ---------------- forward (left-to-right), class = warp+1 ----------------
        const unsigned char cc = (unsigned char)(warp + 1);
        unsigned char cl[16];
        int dp = KBIG, dn = KBIG;
        bool found = false;
        #pragma unroll
        for (int i = 0; i < 16; i++) {
            cl[i] = cls[lane * 16 + i];
            bool m = (cl[i] == cc);
            found |= m;
            dp = m ? dp + 1 : 0;
            dn = m ? 0 : dn + 1;
        }
        int sp = (dp >= KBIG) ? SINF : dp;
        int sn = (dn >= KBIG) ? SINF : dn;
        #pragma unroll
        for (int off = 1; off < 32; off <<= 1) {
            int up_p = __shfl_up_sync(FULL, sp, off);
            int up_n = __shfl_up_sync(FULL, sn, off);
            if (lane >= off) {
                sp = min(up_p + 16 * off, sp);
                sn = min(up_n + 16 * off, sn);
            }
        }
        int ep = __shfl_up_sync(FULL, sp, 1);
        int en = __shfl_up_sync(FULL, sn, 1);
        int carp = (lane == 0) ? 1000000 : min(1000000 + 16 * lane, ep);
        int carn = (lane == 0) ? 1000000 : min(1000000 + 16 * lane, en);
        #pragma unroll
        for (int i = 0; i < 16; i++) {
            bool m = (cl[i] == cc);
            carp = m ? carp + 1 : 0;
            carn = m ? 0 : carn + 1;
            dfp[warp][lane * 16 + i] = (unsigned short)min(carp, 60000);
            dfn[warp][lane * 16 + i] = (unsigned short)min(carn, 60000);
        }
        if (__any_sync(FULL, found) && lane == 0)
            atomicOr(&g_present[n * NCL + warp], 1);
    } else {
        // ---------------- backward (right-to-left), class = warp-2 ----------------
        const int c = warp - NCL;            // 0..2 -> class c+1
        const unsigned char cc = (unsigned char)(c + 1);
        unsigned char cl[16];
        int dp = KBIG, dn = KBIG;
        #pragma unroll
        for (int i = 0; i < 16; i++) {
            cl[i] = cls[WW - 1 - lane * 16 - i];
            bool m = (cl[i] == cc);
            dp = m ? dp + 1 : 0;
            dn = m ? 0 : dn + 1;
        }
        int sp = (dp >= KBIG) ? SINF : dp;
        int sn = (dn >= KBIG) ? SINF : dn;
        #pragma unroll
        for (int off = 1; off < 32; off <<= 1) {
            int up_p = __shfl_up_sync(FULL, sp, off);
            int up_n = __shfl_up_sync(FULL, sn, off);
            if (lane >= off) {
                sp = min(up_p + 16 * off, sp);
                sn = min(up_n + 16 * off, sn);
            }
        }
        int ep = __shfl_up_sync(FULL, sp, 1);
        int en = __shfl_up_sync(FULL, sn, 1);
        int carp = (lane == 0) ? 1000000 : min(1000000 + 16 * lane, ep);
        int carn = (lane == 0) ? 1000000 : min(1000000 + 16 * lane, en);
        #pragma unroll
        for (int i = 0; i < 16; i++) {
            int x = WW - 1 - lane * 16 - i;
            bool m = (cl[i] == cc);
            carp = m ? carp + 1 : 0;
            carn = m ? 0 : carn + 1;
            dbp[c][x] = (unsigned short)min(carp, 60000);
            dbn[c][x] = (unsigned short)min(carn, 60000);
        }
    }
    __syncthreads();

    // ---------------- combine fwd/bwd, stage interleaved ----------------
    #pragma unroll
    for (int k = 0; k < 8; k++) {
        int i2 = k * 192 + tid;              // 0..1535
        int c2 = i2 >> 9;                    // class idx 0..2
        int x  = i2 & (WW - 1);
        unsigned short p = min(dfp[c2][x], dbp[c2][x]);
        unsigned short q = min(dfn[c2][x], dbn[c2][x]);
        gstage[c2][x] = make_ushort2(p, q);  // low=gp, high=gn
    }
    __syncthreads();

    // ---------------- coalesced uint4 write-out ----------------
    // 3*WW uint = 384 uint4; 192 threads -> 2 each. Row of one class = 128 uint4.
    const uint4* s = reinterpret_cast<const uint4*>(&gstage[0][0]);
    uint4* dg = reinterpret_cast<uint4*>(gpn_buf);
    #pragma unroll
    for (int k = 0; k < 2; k++) {
        int i2 = k * 192 + tid;              // 0..383
        int c2 = i2 >> 7;                    // class idx 0..2
        int j  = i2 & 127;                   // uint4 within row
        size_t off = ((size_t)(n * NCL + c2) * HH + r) * (WW / 4) + j;
        dg[off] = s[i2];
    }
}

// ---------------------------------------------------------------------------
// Kernel 2: fused softmax + signed EDT + reduction + tail finalize.
// 2 pixels/thread. Merged pos/neg integer min-plus:
//   exact min_{r'} (r-r')^2 + g^2 for both signs and both pixels from ONE
//   uint2 load per probe row. Clamped indices are dominated (monotone d^2).
// ---------------------------------------------------------------------------
__global__ void __launch_bounds__(256) loss_pass(const float* __restrict__ logits,
                                                 float* __restrict__ out) {
    const int idx = blockIdx.x * 256 + threadIdx.x;   // pair index
    const int x = (idx & 255) * 2;
    const int r = (idx >> 8) & (HH - 1);
    const int n = idx >> 17;
    const int pix = r * WW + x;

    float l0[NC], l1[NC];
    #pragma unroll
    for (int c = 0; c < NC; c++) {
        float2 v = *reinterpret_cast<const float2*>(
            logits + (size_t)(n * NC + c) * (HH * WW) + pix);
        l0[c] = v.x; l1[c] = v.y;
    }
    float mx0 = fmaxf(fmaxf(l0[0], l0[1]), fmaxf(l0[2], l0[3]));
    float mx1 = fmaxf(fmaxf(l1[0], l1[1]), fmaxf(l1[2], l1[3]));
    float e0[NC], e1[NC], s0 = 0.0f, s1 = 0.0f;
    #pragma unroll
    for (int c = 0; c < NC; c++) {
        e0[c] = __expf(l0[c] - mx0); s0 += e0[c];
        e1[c] = __expf(l1[c] - mx1); s1 += e1[c];
    }
    float inv0 = 1.0f / s0, inv1 = 1.0f / s1;

    float acc0 = 0.0f, acc1 = 0.0f;
    #pragma unroll 1
    for (int ci = 0; ci < NCL; ci++) {        // classes 1..3
        if (!g_present[n * NCL + ci]) continue;
        const unsigned int* col = gpn_buf + ((size_t)(n * NCL + ci) * HH) * WW + x;

        uint2 w = *reinterpret_cast<const uint2*>(col + r * WW);
        unsigned int gp0 = w.x & 0xffffu, gn0 = w.x >> 16;
        unsigned int gp1 = w.y & 0xffffu, gn1 = w.y >> 16;
        unsigned int bp0 = gp0 * gp0, bn0 = gn0 * gn0;
        unsigned int bp1 = gp1 * gp1, bn1 = gn1 * gn1;
        unsigned int bmax = max(max(bp0, bn0), max(bp1, bn1));

        if (bmax > 1u) {
            #pragma unroll
            for (int d = 1; d <= 2; d++) {
                uint2 wu = *reinterpret_cast<const uint2*>(col + max(r - d, 0) * WW);
                uint2 wd = *reinterpret_cast<const uint2*>(col + min(r + d, HH - 1) * WW);
                unsigned int dd = (unsigned int)(d * d);
                unsigned int t;
                t = wu.x & 0xffffu; bp0 = min(bp0, t * t + dd);
                t = wu.x >> 16;     bn0 = min(bn0, t * t + dd);
                t = wu.y & 0xffffu; bp1 = min(bp1, t * t + dd);
                t = wu.y >> 16;     bn1 = min(bn1, t * t + dd);
                t = wd.x & 0xffffu; bp0 = min(bp0, t * t + dd);
                t = wd.x >> 16;     bn0 = min(bn0, t * t + dd);
                t = wd.y & 0xffffu; bp1 = min(bp1, t * t + dd);
                t = wd.y >> 16;     bn1 = min(bn1, t * t + dd);
            }
            bmax = max(max(bp0, bn0), max(bp1, bn1));
            #pragma unroll 1
            for (int d = 3; (unsigned int)(d * d) < bmax; ++d) {
                uint2 wu = *reinterpret_cast<const uint2*>(col + max(r - d, 0) * WW);
                uint2 wd = *reinterpret_cast<const uint2*>(col + min(r + d, HH - 1) * WW);
                unsigned int dd = (unsigned int)(d * d);
                unsigned int t;
                t = wu.x & 0xffffu; bp0 = min(bp0, t * t + dd);
                t = wu.x >> 16;     bn0 = min(bn0, t * t + dd);
                t = wu.y & 0xffffu; bp1 = min(bp1, t * t + dd);
                t = wu.y >> 16;     bn1 = min(bn1, t * t + dd);
                t = wd.x & 0xffffu; bp0 = min(bp0, t * t + dd);
                t = wd.x >> 16;     bn0 = min(bn0, t * t + dd);
                t = wd.y & 0xffffu; bp1 = min(bp1, t * t + dd);
                t = wd.y >> 16;     bn1 = min(bn1, t * t + dd);
                bmax = max(max(bp0, bn0), max(bp1, bn1));
            }
        }
        const int c = ci + 1;
        acc0 += (e0[c] * inv0) * (sqrtf((float)bn0) - sqrtf((float)bp0));
        acc1 += (e1[c] * inv1) * (sqrtf((float)bn1) - sqrtf((float)bp1));
    }
    double local = (double)acc0 + (double)acc1;

    // block reduction (double)
    __shared__ double warp_sums[8];
    __shared__ bool is_last;
    const unsigned FULL = 0xffffffffu;
    #pragma unroll
    for (int off = 16; off > 0; off >>= 1)
        local += __shfl_down_sync(FULL, local, off);
    const int lane = threadIdx.x & 31;
    const int wid = threadIdx.x >> 5;
    if (lane == 0) warp_sums[wid] = local;
    __syncthreads();
    if (wid == 0) {
        double v = (lane < 8) ? warp_sums[lane] : 0.0;
        #pragma unroll
        for (int off = 4; off > 0; off >>= 1)
            v += __shfl_down_sync(FULL, v, off);
        if (lane == 0) {
            atomicAdd(&g_acc, v);
            __threadfence();
            unsigned int t = atomicAdd(&g_count, 1u);
            is_last = (t == gridDim.x - 1);
        }
    }
    __syncthreads();
    // Last block finalizes and restores all device state (deterministic replay)
    if (is_last) {
        if (threadIdx.x == 0) {
            __threadfence();
            double total = g_acc;
            // mean over N*C*H*W = 2*4*512*512 = 2^21 elements
            out[0] = (float)(total * (1.0 / 2097152.0));
            g_acc = 0.0;
            g_count = 0u;
        }
        if (threadIdx.x < NPRES) g_present[threadIdx.x] = 0;
    }
}

extern "C" void kernel_launch(void* const* d_in, const int* in_sizes, int n_in,
                              void* d_out, int out_size) {
    const float* logits = (const float*)d_in[0];     // [2,4,512,512] fp32
    const int* tgt_words = (const int*)d_in[1];      // [2,512,512] int32 or int64
    float* out = (float*)d_out;

    row_pass<<<NB * HH, 192>>>(tgt_words);
    loss_pass<<<NPIX / 512, 256>>>(logits, out);
}

// round 9
// speedup vs baseline: 2.5189x; 1.0657x over previous
#include <cuda_runtime.h>
#include <stdint.h>

#define HH 512
#define WW 512
#define NB 2
#define NC 4
#define NCL 3                 // classes 1..3 only (class 0 masked by reference)
#define NPRES (NB*NCL)
#define NPIX (NB*HH*WW)

// Interleaved scratch: per pixel one uint = gp (low 16) | gn (high 16),
// for classes 1..3 only. 2*3*512*512*4 B = 6.3 MB (L2-resident).
__device__ __align__(16) unsigned int gpn_buf[(size_t)NB*NCL*HH*WW];
__device__ double g_acc;            // static-init 0; reset by last loss block
__device__ unsigned int g_count;    // static-init 0; reset by last loss block
__device__ int g_present[NPRES];    // static-init 0; reset by last loss block

// ---------------------------------------------------------------------------
// Kernel 1: row pass. One block per (n, r). 192 threads:
//   warps 0-2: forward scan for classes 1-3; warps 3-5: backward scan.
// Inline dtype probe: int64 labels (0..3) have all odd 32-bit words zero.
// g = min(fwd, bwd) distance-to-False, reference carry init 1e6 (clamped 60000).
// ---------------------------------------------------------------------------
__global__ void __launch_bounds__(192) row_pass(const int* __restrict__ tgt_words) {
    __shared__ unsigned char cls[WW];
    __shared__ unsigned short dfp[NCL][WW], dfn[NCL][WW];   // forward
    __shared__ unsigned short dbp[NCL][WW], dbn[NCL][WW];   // backward
    __shared__ __align__(16) ushort2 gstage[NCL][WW];       // combined (gp,gn)

    const int blk = blockIdx.x;          // n*H + r
    const int n = blk >> 9;
    const int r = blk & (HH - 1);
    const int tid = threadIdx.x;

    const size_t elem_base = ((size_t)n * HH + r) * WW;

    // Probe + load (threads 0..127 cover the row; int32 view always in-bounds)
    int4 v; int myodd = 0;
    if (tid < 128) {
        v = reinterpret_cast<const int4*>(tgt_words + elem_base)[tid];
        myodd = v.y | v.w;
    }
    if (__syncthreads_or(myodd)) {
        if (tid < 128) {
            cls[4 * tid + 0] = (unsigned char)v.x;
            cls[4 * tid + 1] = (unsigned char)v.y;
            cls[4 * tid + 2] = (unsigned char)v.z;
            cls[4 * tid + 3] = (unsigned char)v.w;
        }
    } else {
        if (tid < 128) {
            const longlong4 q = reinterpret_cast<const longlong4*>(
                tgt_words + 2 * elem_base)[tid];
            cls[4 * tid + 0] = (unsigned char)q.x;
            cls[4 * tid + 1] = (unsigned char)q.y;
            cls[4 * tid + 2] = (unsigned char)q.z;
            cls[4 * tid + 3] = (unsigned char)q.w;
        }
    }
    __syncthreads();

    const int warp = tid >> 5;
    const int lane = tid & 31;
    const int KBIG = 1 << 20;
    const int SINF = 1 << 26;
    const unsigned FULL = 0xffffffffu;

    if (warp < NCL) {
        // ---------------- forward (left-to-right), class = warp+1 ----------------
        const unsigned char cc = (unsigned char)(warp + 1);
        unsigned char cl[16];
        int dp = KBIG, dn = KBIG;
        bool found = false;
        #pragma unroll
        for (int i = 0; i < 16; i++) {
            cl[i] = cls[lane * 16 + i];
            bool m = (cl[i] == cc);
            found |= m;
            dp = m ? dp + 1 : 0;
            dn = m ? 0 : dn + 1;
        }
        int sp = (dp >= KBIG) ? SINF : dp;
        int sn = (dn >= KBIG) ? SINF : dn;
        #pragma unroll
        for (int off = 1; off < 32; off <<= 1) {
            int up_p = __shfl_up_sync(FULL, sp, off);
            int up_n = __shfl_up_sync(FULL, sn, off);
            if (lane >= off) {
                sp = min(up_p + 16 * off, sp);
                sn = min(up_n + 16 * off, sn);
            }
        }
        int ep = __shfl_up_sync(FULL, sp, 1);
        int en = __shfl_up_sync(FULL, sn, 1);
        int carp = (lane == 0) ? 1000000 : min(1000000 + 16 * lane, ep);
        int carn = (lane == 0) ? 1000000 : min(1000000 + 16 * lane, en);
        #pragma unroll
        for (int i = 0; i < 16; i++) {
            bool m = (cl[i] == cc);
            carp = m ? carp + 1 : 0;
            carn = m ? 0 : carn + 1;
            dfp[warp][lane * 16 + i] = (unsigned short)min(carp, 60000);
            dfn[warp][lane * 16 + i] = (unsigned short)min(carn, 60000);
        }
        if (__any_sync(FULL, found) && lane == 0)
            atomicOr(&g_present[n * NCL + warp], 1);
    } else {
        // ---------------- backward (right-to-left), class = warp-2 ----------------
        const int c = warp - NCL;            // 0..2 -> class c+1
        const unsigned char cc = (unsigned char)(c + 1);
        unsigned char cl[16];
        int dp = KBIG, dn = KBIG;
        #pragma unroll
        for (int i = 0; i < 16; i++) {
            cl[i] = cls[WW - 1 - lane * 16 - i];
            bool m = (cl[i] == cc);
            dp = m ? dp + 1 : 0;
            dn = m ? 0 : dn + 1;
        }
        int sp = (dp >= KBIG) ? SINF : dp;
        int sn = (dn >= KBIG) ? SINF : dn;
        #pragma unroll
        for (int off = 1; off < 32; off <<= 1) {
            int up_p = __shfl_up_sync(FULL, sp, off);
            int up_n = __shfl_up_sync(FULL, sn, off);
            if (lane >= off) {
                sp = min(up_p + 16 * off, sp);
                sn = min(up_n + 16 * off, sn);
            }
        }
        int ep = __shfl_up_sync(FULL, sp, 1);
        int en = __shfl_up_sync(FULL, sn, 1);
        int carp = (lane == 0) ? 1000000 : min(1000000 + 16 * lane, ep);
        int carn = (lane == 0) ? 1000000 : min(1000000 + 16 * lane, en);
        #pragma unroll
        for (int i = 0; i < 16; i++) {
            int x = WW - 1 - lane * 16 - i;
            bool m = (cl[i] == cc);
            carp = m ? carp + 1 : 0;
            carn = m ? 0 : carn + 1;
            dbp[c][x] = (unsigned short)min(carp, 60000);
            dbn[c][x] = (unsigned short)min(carn, 60000);
        }
    }
    __syncthreads();

    // ---------------- combine fwd/bwd, stage interleaved ----------------
    #pragma unroll
    for (int k = 0; k < 8; k++) {
        int i2 = k * 192 + tid;              // 0..1535
        int c2 = i2 >> 9;                    // class idx 0..2
        int x  = i2 & (WW - 1);
        unsigned short p = min(dfp[c2][x], dbp[c2][x]);
        unsigned short q = min(dfn[c2][x], dbn[c2][x]);
        gstage[c2][x] = make_ushort2(p, q);  // low=gp, high=gn
    }
    __syncthreads();

    // ---------------- coalesced uint4 write-out ----------------
    const uint4* s = reinterpret_cast<const uint4*>(&gstage[0][0]);
    uint4* dg = reinterpret_cast<uint4*>(gpn_buf);
    #pragma unroll
    for (int k = 0; k < 2; k++) {
        int i2 = k * 192 + tid;              // 0..383
        int c2 = i2 >> 7;                    // class idx 0..2
        int j  = i2 & 127;                   // uint4 within row
        size_t off = ((size_t)(n * NCL + c2) * HH + r) * (WW / 4) + j;
        dg[off] = s[i2];
    }
}

// ---------------------------------------------------------------------------
// Kernel 2: fused softmax + signed EDT + reduction + tail finalize.
// 4 pixels/thread, classes fully unrolled for cross-class MLP:
//   phase 1: 3 center uint4 loads in flight; phase 2: 12 window uint4 loads;
//   phase 3: rare per-class serial tails. Absent classes are masked to 0 at
//   the center (mins can never rise, tail skipped, term exactly 0).
// Clamped probe rows are dominated by earlier-visited true offsets.
// ---------------------------------------------------------------------------
__global__ void __launch_bounds__(256) loss_pass(const float* __restrict__ logits,
                                                 float* __restrict__ out) {
    const int idx = blockIdx.x * 256 + threadIdx.x;   // quad index
    const int x = (idx & 127) * 4;
    const int r = (idx >> 7) & (HH - 1);
    const int n = idx >> 16;
    const int pix = r * WW + x;

    // ---- softmax probs for classes 1..3, 4 pixels ----
    float4 lv[NC];
    #pragma unroll
    for (int c = 0; c < NC; c++)
        lv[c] = *reinterpret_cast<const float4*>(
            logits + (size_t)(n * NC + c) * (HH * WW) + pix);
    float prob[NCL][4];
    {
        float l[NC], mx, s, inv;
        #pragma unroll
        for (int j = 0; j < 4; j++) {
            l[0] = (&lv[0].x)[j]; l[1] = (&lv[1].x)[j];
            l[2] = (&lv[2].x)[j]; l[3] = (&lv[3].x)[j];
            mx = fmaxf(fmaxf(l[0], l[1]), fmaxf(l[2], l[3]));
            float e0 = __expf(l[0] - mx), e1 = __expf(l[1] - mx);
            float e2 = __expf(l[2] - mx), e3 = __expf(l[3] - mx);
            s = e0 + e1 + e2 + e3;
            inv = 1.0f / s;
            prob[0][j] = e1 * inv;
            prob[1][j] = e2 * inv;
            prob[2][j] = e3 * inv;
        }
    }

    // ---- phase 1: presence + center loads (3 independent) ----
    const unsigned int* col[NCL];
    unsigned int pres[NCL];
    uint4 wc[NCL];
    #pragma unroll
    for (int ci = 0; ci < NCL; ci++) {
        pres[ci] = (unsigned int)g_present[n * NCL + ci];
        col[ci] = gpn_buf + ((size_t)(n * NCL + ci) * HH) * WW + x;
        wc[ci] = *reinterpret_cast<const uint4*>(col[ci] + r * WW);
    }
    unsigned int bp[NCL][4], bn[NCL][4];
    #pragma unroll
    for (int ci = 0; ci < NCL; ci++) {
        #pragma unroll
        for (int j = 0; j < 4; j++) {
            unsigned int w = (&wc[ci].x)[j];
            unsigned int gp = w & 0xffffu, gn = w >> 16;
            bp[ci][j] = pres[ci] ? gp * gp : 0u;   // masked center: absent -> 0
            bn[ci][j] = pres[ci] ? gn * gn : 0u;
        }
    }

    // ---- phase 2: window d=1,2 — 12 independent loads ----
    const int ru1 = max(r - 1, 0) * WW, rd1 = min(r + 1, HH - 1) * WW;
    const int ru2 = max(r - 2, 0) * WW, rd2 = min(r + 2, HH - 1) * WW;
    #pragma unroll
    for (int ci = 0; ci < NCL; ci++) {
        uint4 u1 = *reinterpret_cast<const uint4*>(col[ci] + ru1);
        uint4 d1 = *reinterpret_cast<const uint4*>(col[ci] + rd1);
        uint4 u2 = *reinterpret_cast<const uint4*>(col[ci] + ru2);
        uint4 d2 = *reinterpret_cast<const uint4*>(col[ci] + rd2);
        #pragma unroll
        for (int j = 0; j < 4; j++) {
            unsigned int t;
            t = (&u1.x)[j] & 0xffffu; bp[ci][j] = min(bp[ci][j], t * t + 1u);
            t = (&u1.x)[j] >> 16;     bn[ci][j] = min(bn[ci][j], t * t + 1u);
            t = (&d1.x)[j] & 0xffffu; bp[ci][j] = min(bp[ci][j], t * t + 1u);
            t = (&d1.x)[j] >> 16;     bn[ci][j] = min(bn[ci][j], t * t + 1u);
            t = (&u2.x)[j] & 0xffffu; bp[ci][j] = min(bp[ci][j], t * t + 4u);
            t = (&u2.x)[j] >> 16;     bn[ci][j] = min(bn[ci][j], t * t + 4u);
            t = (&d2.x)[j] & 0xffffu; bp[ci][j] = min(bp[ci][j], t * t + 4u);
            t = (&d2.x)[j] >> 16;     bn[ci][j] = min(bn[ci][j], t * t + 4u);
        }
    }

    // ---- phase 3: rare serial tails, per class ----
    #pragma unroll
    for (int ci = 0; ci < NCL; ci++) {
        unsigned int bmax = 0u;
        #pragma unroll
        for (int j = 0; j < 4; j++) bmax = max(bmax, max(bp[ci][j], bn[ci][j]));
        #pragma unroll 1
        for (int d = 3; (unsigned int)(d * d) < bmax; ++d) {
            const uint4 wu = *reinterpret_cast<const uint4*>(col[ci] + max(r - d, 0) * WW);
            const uint4 wd = *reinterpret_cast<const uint4*>(col[ci] + min(r + d, HH - 1) * WW);
            unsigned int dd = (unsigned int)(d * d);
            bmax = 0u;
            #pragma unroll
            for (int j = 0; j < 4; j++) {
                unsigned int t;
                t = (&wu.x)[j] & 0xffffu; bp[ci][j] = min(bp[ci][j], t * t + dd);
                t = (&wu.x)[j] >> 16;     bn[ci][j] = min(bn[ci][j], t * t + dd);
                t = (&wd.x)[j] & 0xffffu; bp[ci][j] = min(bp[ci][j], t * t + dd);
                t = (&wd.x)[j] >> 16;     bn[ci][j] = min(bn[ci][j], t * t + dd);
                bmax = max(bmax, max(bp[ci][j], bn[ci][j]));
            }
        }
    }

    // ---- accumulate ----
    float acc = 0.0f;
    #pragma unroll
    for (int ci = 0; ci < NCL; ci++)
        #pragma unroll
        for (int j = 0; j < 4; j++)
            acc += prob[ci][j] * (sqrtf((float)bn[ci][j]) - sqrtf((float)bp[ci][j]));
    double local = (double)acc;

    // ---- block reduction (double) + tail finalize ----
    __shared__ double warp_sums[8];
    __shared__ bool is_last;
    const unsigned FULL = 0xffffffffu;
    #pragma unroll
    for (int off = 16; off > 0; off >>= 1)
        local += __shfl_down_sync(FULL, local, off);
    const int lane = threadIdx.x & 31;
    const int wid = threadIdx.x >> 5;
    if (lane == 0) warp_sums[wid] = local;
    __syncthreads();
    if (wid == 0) {
        double v = (lane < 8) ? warp_sums[lane] : 0.0;
        #pragma unroll
        for (int off = 4; off > 0; off >>= 1)
            v += __shfl_down_sync(FULL, v, off);
        if (lane == 0) {
            atomicAdd(&g_acc, v);
            __threadfence();
            unsigned int t = atomicAdd(&g_count, 1u);
            is_last = (t == gridDim.x - 1);
        }
    }
    __syncthreads();
    // Last block finalizes and restores all device state (deterministic replay)
    if (is_last) {
        if (threadIdx.x == 0) {
            __threadfence();
            double total = g_acc;
            // mean over N*C*H*W = 2*4*512*512 = 2^21 elements
            out[0] = (float)(total * (1.0 / 2097152.0));
            g_acc = 0.0;
            g_count = 0u;
        }
        if (threadIdx.x < NPRES) g_present[threadIdx.x] = 0;
    }
}

extern "C" void kernel_launch(void* const* d_in, const int* in_sizes, int n_in,
                              void* d_out, int out_size) {
    const float* logits = (const float*)d_in[0];     // [2,4,512,512] fp32
    const int* tgt_words = (const int*)d_in[1];      // [2,512,512] int32 or int64
    float* out = (float*)d_out;

    row_pass<<<NB * HH, 192>>>(tgt_words);
    loss_pass<<<NPIX / 1024, 256>>>(logits, out);
}